// round 17
// baseline (speedup 1.0000x reference)
#include <cuda_runtime.h>
#include <cuda_fp16.h>
#include <cstdint>

// Problem constants (B=64, H=W=56, C=256, heads=8, hd=32, ws=7, shift=3)
#define IMG 56
#define CH 256
#define NHEAD 8
#define HD 32
#define WS 7
#define NWIN 64
#define NTOK 49
#define BATCH 64
#define M_TOTAL (BATCH * IMG * IMG)   // 200704
#define QKV_N 768
#define QSCALE 0.17677669529663687f

// Scratch (fp16 end-to-end)
// g_qkv layout: [24][M_TOTAL][32] halfs; chunk c = qtype*8 + head (q pre-scaled)
__device__ __half g_xh[(size_t)M_TOTAL * CH];
__device__ __half g_wq[(size_t)QKV_N * CH];
__device__ __half g_wp[(size_t)CH * CH];
__device__ __half g_qkv[(size_t)M_TOTAL * QKV_N];
__device__ __half g_attnout[(size_t)M_TOTAL * CH];

// ---- index helper ------------------------------------------------------
__device__ __forceinline__ int gather_src_row(int m) {
    int win = m / NTOK, n = m - win * NTOK;
    int b = win >> 6, wl = win & 63;
    int hr = (wl >> 3) * WS + n / WS;
    int wr = (wl & 7) * WS + n % WS;
    int h = hr + 3; if (h >= IMG) h -= IMG;
    int w = wr + 3; if (w >= IMG) w -= IMG;
    return (b * IMG + h) * IMG + w;
}

__device__ __forceinline__ uint32_t pack_h2(float a, float b) {
    __half2 h = __floats2half2_rn(a, b);
    return *reinterpret_cast<uint32_t*>(&h);
}

__device__ __forceinline__ void mma16816(float* c,
    uint32_t a0, uint32_t a1, uint32_t a2, uint32_t a3,
    uint32_t b0, uint32_t b1) {
    asm volatile(
        "mma.sync.aligned.m16n8k16.row.col.f32.f16.f16.f32 "
        "{%0,%1,%2,%3}, {%4,%5,%6,%7}, {%8,%9}, {%0,%1,%2,%3};"
        : "+f"(c[0]), "+f"(c[1]), "+f"(c[2]), "+f"(c[3])
        : "r"(a0), "r"(a1), "r"(a2), "r"(a3), "r"(b0), "r"(b1));
}

__device__ __forceinline__ void cp_async16(uint32_t dst, const void* src) {
    asm volatile("cp.async.cg.shared.global [%0], [%1], 16;" :: "r"(dst), "l"(src));
}
__device__ __forceinline__ void cp_commit() { asm volatile("cp.async.commit_group;"); }
template <int N>
__device__ __forceinline__ void cp_wait() { asm volatile("cp.async.wait_group %0;" :: "n"(N)); }

// ---- prep kernels (one-time fp32 -> fp16) -------------------------------
__global__ void __launch_bounds__(256) prep_x(const float* __restrict__ x) {
    int idx = blockIdx.x * 256 + threadIdx.x;
    int m = idx >> 6;
    int k4 = (idx & 63) * 4;
    float4 v = *(const float4*)(x + (size_t)gather_src_row(m) * CH + k4);
    uint2 r;
    r.x = pack_h2(v.x, v.y);
    r.y = pack_h2(v.z, v.w);
    *(uint2*)(g_xh + (size_t)m * CH + k4) = r;
}

__global__ void __launch_bounds__(256) prep_w(const float* __restrict__ w,
                                              __half* __restrict__ wh) {
    int idx = blockIdx.x * 256 + threadIdx.x;
    float4 v = *(const float4*)(w + (size_t)idx * 4);
    uint2 r;
    r.x = pack_h2(v.x, v.y);
    r.y = pack_h2(v.z, v.w);
    *(uint2*)(wh + (size_t)idx * 4) = r;
}

// ---- HMMA GEMM: 128x128 tile, 256 threads, 2 CTAs/SM, 4-stage cp.async -
#define BK 32
#define SA 40
#define A_ELEMS (128 * SA)
#define B_ELEMS (128 * SA)
#define A_BYTES (A_ELEMS * 2)
#define STG_ELEMS (A_ELEMS + B_ELEMS)
#define STG_BYTES (STG_ELEMS * 2)          // 20480
#define NPIPE 4
#define SMEM_GEMM (NPIPE * STG_BYTES)      // 81920 per CTA

template <int MODE>
__global__ void __launch_bounds__(256, 2) tc_gemm(
    const __half* __restrict__ Ain, const __half* __restrict__ Win,
    const float* __restrict__ bias, void* __restrict__ outptr)
{
    extern __shared__ __half sm[];
    const int tid = threadIdx.x;
    const int wid = tid >> 5;
    const int lane = tid & 31;
    const int gid = lane >> 2;
    const int t4 = lane & 3;
    const int wm = wid & 3;
    const int wn = wid >> 2;
    const int bm = blockIdx.y * 128;
    const int bn = blockIdx.x * 128;

    const uint32_t smem_base = (uint32_t)__cvta_generic_to_shared(sm);

    const int lrow = tid >> 1;
    const int lk = (tid & 1) * 16;
    const __half* Ag = Ain + (size_t)(bm + lrow) * CH + lk;
    const __half* Bg = Win + (size_t)(bn + lrow) * CH + lk;

    const uint32_t sA = (uint32_t)((lrow * SA + lk) * 2);
    const uint32_t sB = (uint32_t)(A_BYTES + (lrow * SA + lk) * 2);

    auto load_stage = [&](int st, int k0) {
        const uint32_t base = smem_base + st * STG_BYTES;
        cp_async16(base + sA, Ag + k0);
        cp_async16(base + sA + 16, Ag + k0 + 8);
        cp_async16(base + sB, Bg + k0);
        cp_async16(base + sB + 16, Bg + k0 + 8);
        cp_commit();
    };

    float acc[2][8][4];
#pragma unroll
    for (int mt = 0; mt < 2; mt++)
#pragma unroll
        for (int nt = 0; nt < 8; nt++)
#pragma unroll
            for (int r = 0; r < 4; r++) acc[mt][nt][r] = 0.f;

    load_stage(0, 0);
    load_stage(1, BK);
    load_stage(2, 2 * BK);

    const int NSTAGE = CH / BK;   // 8
    for (int s = 0; s < NSTAGE; s++) {
        cp_wait<2>();
        __syncthreads();
        if (s + 3 < NSTAGE) load_stage((s + 3) & (NPIPE - 1), (s + 3) * BK);

        const __half* Ah = sm + (s & (NPIPE - 1)) * STG_ELEMS;
        const __half* Bh = Ah + A_ELEMS;
#pragma unroll
        for (int ksub = 0; ksub < 2; ksub++) {
            const int kk = ksub * 16 + 2 * t4;
            uint32_t ah[2][4];
#pragma unroll
            for (int mt = 0; mt < 2; mt++) {
                int r = wm * 32 + mt * 16 + gid;
                ah[mt][0] = *(const uint32_t*)(Ah + r * SA + kk);
                ah[mt][1] = *(const uint32_t*)(Ah + (r + 8) * SA + kk);
                ah[mt][2] = *(const uint32_t*)(Ah + r * SA + kk + 8);
                ah[mt][3] = *(const uint32_t*)(Ah + (r + 8) * SA + kk + 8);
            }
#pragma unroll
            for (int nt = 0; nt < 8; nt++) {
                int c = wn * 64 + nt * 8 + gid;
                uint32_t b0 = *(const uint32_t*)(Bh + c * SA + kk);
                uint32_t b1 = *(const uint32_t*)(Bh + c * SA + kk + 8);
                mma16816(acc[0][nt], ah[0][0], ah[0][1], ah[0][2], ah[0][3], b0, b1);
                mma16816(acc[1][nt], ah[1][0], ah[1][1], ah[1][2], ah[1][3], b0, b1);
            }
        }
    }

    // epilogue
#pragma unroll
    for (int mt = 0; mt < 2; mt++) {
        int m1 = bm + wm * 32 + mt * 16 + gid;
        int m2 = m1 + 8;
        if (MODE == 0) {
            __half* o = (__half*)outptr;
#pragma unroll
            for (int nt = 0; nt < 8; nt++) {
                int n = bn + wn * 64 + nt * 8 + 2 * t4;
                int cch = n >> 5, d = n & 31;
                float2 bv2 = *(const float2*)(bias + n);
                float sc = (n < 256) ? QSCALE : 1.0f;
                *(uint32_t*)(o + ((size_t)cch * M_TOTAL + m1) * 32 + d) =
                    pack_h2((acc[mt][nt][0] + bv2.x) * sc, (acc[mt][nt][1] + bv2.y) * sc);
                *(uint32_t*)(o + ((size_t)cch * M_TOTAL + m2) * 32 + d) =
                    pack_h2((acc[mt][nt][2] + bv2.x) * sc, (acc[mt][nt][3] + bv2.y) * sc);
            }
        } else {
            float* d1 = (float*)outptr + (size_t)gather_src_row(m1) * CH;
            float* d2 = (float*)outptr + (size_t)gather_src_row(m2) * CH;
#pragma unroll
            for (int nt = 0; nt < 8; nt++) {
                int n = bn + wn * 64 + nt * 8 + 2 * t4;
                float2 bv2 = *(const float2*)(bias + n);
                float2 r1, r2;
                r1.x = acc[mt][nt][0] + bv2.x; r1.y = acc[mt][nt][1] + bv2.y;
                r2.x = acc[mt][nt][2] + bv2.x; r2.y = acc[mt][nt][3] + bv2.y;
                *(float2*)(d1 + n) = r1;
                *(float2*)(d2 + n) = r2;
            }
        }
    }
}

// ---- HMMA window attention: one CTA per window, one warp per head ------
// per-head smem: KH 1088 u32 | VTH 1056 u32 | TBL 169 f32 -> 2320 words
#define HEAD_WORDS 2320
#define SMEM_ATTN (NHEAD * HEAD_WORDS * 4)   // 74240 bytes

__global__ void __launch_bounds__(256, 2) attn_mma_kernel(
    const __half* __restrict__ qkv, const float* __restrict__ table,
    __half* __restrict__ out)
{
    extern __shared__ uint32_t smw[];
    const int tid = threadIdx.x;
    const int head = tid >> 5;          // warp = head
    const int lane = tid & 31;
    const int gid = lane >> 2;
    const int t4 = lane & 3;
    const int win = blockIdx.x;
    const int wl = win & 63;
    const int hbase = (wl >> 3) * WS;
    const int wbase = (wl & 7) * WS;

    uint32_t* KH = smw + head * HEAD_WORDS;
    uint32_t* VTH = KH + 1088;
    float* TBL = (float*)(VTH + 1056);

    for (int t = lane; t < 169; t += 32) TBL[t] = table[t * NHEAD + head];

    const __half* qbase = qkv + ((size_t)(head)      * M_TOTAL + (size_t)win * NTOK) * HD;
    const __half* kbase = qkv + ((size_t)(8 + head)  * M_TOTAL + (size_t)win * NTOK) * HD;
    const __half* vbase = qkv + ((size_t)(16 + head) * M_TOTAL + (size_t)win * NTOK) * HD;

    // K: contiguous coalesced copy (49*32 halfs = 196 uint4)
    for (int idx = lane; idx < 196; idx += 32) {
        int e = idx * 8;
        int r = e >> 5;
        int c2 = (e & 31) >> 1;
        uint4 kv = *(const uint4*)(kbase + e);
        KH[r * 17 + c2 + 0] = kv.x;
        KH[r * 17 + c2 + 1] = kv.y;
        KH[r * 17 + c2 + 2] = kv.z;
        KH[r * 17 + c2 + 3] = kv.w;
    }
    for (int w = lane; w < 15 * 16; w += 32) {
        int r = 49 + w / 16;
        KH[r * 17 + (w & 15)] = 0u;
    }

    // V transposed: per token, 32 lanes read 64B contiguous
#pragma unroll 4
    for (int tp = 0; tp < 32; tp++) {
        int t0 = 2 * tp, t1 = 2 * tp + 1;
        __half a = (t0 < NTOK) ? vbase[t0 * HD + lane] : __half(0.f);
        __half b = (t1 < NTOK) ? vbase[t1 * HD + lane] : __half(0.f);
        __half2 h = __halves2half2(a, b);
        VTH[lane * 33 + tp] = *reinterpret_cast<uint32_t*>(&h);
    }
    __syncwarp();

    float o[4][4][4];
#pragma unroll
    for (int a = 0; a < 4; a++)
#pragma unroll
        for (int b = 0; b < 4; b++)
#pragma unroll
            for (int r = 0; r < 4; r++) o[a][b][r] = 0.f;

#pragma unroll
    for (int mt = 0; mt < 4; mt++) {
        const int r0 = mt * 16 + gid;
        const int rc0 = min(r0, NTOK - 1);
        const int rc1 = min(r0 + 8, NTOK - 1);
        const __half* q0 = qbase + rc0 * HD;
        const __half* q1 = qbase + rc1 * HD;

        uint32_t qh[2][4];
#pragma unroll
        for (int ks = 0; ks < 2; ks++) {
            const int f0 = ks * 16 + 2 * t4;
            qh[ks][0] = *(const uint32_t*)(q0 + f0);
            qh[ks][1] = *(const uint32_t*)(q1 + f0);
            qh[ks][2] = *(const uint32_t*)(q0 + f0 + 8);
            qh[ks][3] = *(const uint32_t*)(q1 + f0 + 8);
        }

        float c[8][4];
#pragma unroll
        for (int nt = 0; nt < 8; nt++) { c[nt][0] = c[nt][1] = c[nt][2] = c[nt][3] = 0.f; }
#pragma unroll
        for (int nt = 0; nt < 8; nt++) {
            int cn = nt * 8 + gid;
#pragma unroll
            for (int ks = 0; ks < 2; ks++) {
                int cp = ks * 8 + t4;
                uint32_t b0 = KH[cn * 17 + cp], b1 = KH[cn * 17 + cp + 4];
                mma16816(c[nt], qh[ks][0], qh[ks][1], qh[ks][2], qh[ks][3], b0, b1);
            }
        }

        const int ih0 = rc0 / WS, iw0 = rc0 % WS;
        const int ih1 = rc1 / WS, iw1 = rc1 % WS;
        int hr, wr, rh, rw;
        hr = hbase + ih0; wr = wbase + iw0;
        rh = (hr < 49) ? 0 : ((hr < 53) ? 1 : 2); rw = (wr < 49) ? 0 : ((wr < 53) ? 1 : 2);
        const int rg0 = rh * 3 + rw;
        hr = hbase + ih1; wr = wbase + iw1;
        rh = (hr < 49) ? 0 : ((hr < 53) ? 1 : 2); rw = (wr < 49) ? 0 : ((wr < 53) ? 1 : 2);
        const int rg1 = rh * 3 + rw;

#pragma unroll
        for (int nt = 0; nt < 8; nt++) {
#pragma unroll
            for (int jc = 0; jc < 2; jc++) {
                int j = nt * 8 + 2 * t4 + jc;
                if (j < NTOK) {
                    int jh = j / WS, jw = j % WS;
                    int jhr = hbase + jh, jwr = wbase + jw;
                    int rjh = (jhr < 49) ? 0 : ((jhr < 53) ? 1 : 2);
                    int rjw = (jwr < 49) ? 0 : ((jwr < 53) ? 1 : 2);
                    int rgj = rjh * 3 + rjw;
                    float b0 = TBL[(ih0 - jh + 6) * 13 + (iw0 - jw + 6)];
                    float b1 = TBL[(ih1 - jh + 6) * 13 + (iw1 - jw + 6)];
                    if (rg0 != rgj) b0 -= 100.f;
                    if (rg1 != rgj) b1 -= 100.f;
                    c[nt][jc] += b0;
                    c[nt][2 + jc] += b1;
                } else {
                    c[nt][jc] = -1e30f;
                    c[nt][2 + jc] = -1e30f;
                }
            }
        }

        float m0 = -1e30f, m1 = -1e30f;
#pragma unroll
        for (int nt = 0; nt < 8; nt++) {
            m0 = fmaxf(m0, fmaxf(c[nt][0], c[nt][1]));
            m1 = fmaxf(m1, fmaxf(c[nt][2], c[nt][3]));
        }
        m0 = fmaxf(m0, __shfl_xor_sync(0xffffffffu, m0, 1));
        m0 = fmaxf(m0, __shfl_xor_sync(0xffffffffu, m0, 2));
        m1 = fmaxf(m1, __shfl_xor_sync(0xffffffffu, m1, 1));
        m1 = fmaxf(m1, __shfl_xor_sync(0xffffffffu, m1, 2));
        float s0 = 0.f, s1 = 0.f;
#pragma unroll
        for (int nt = 0; nt < 8; nt++) {
            c[nt][0] = __expf(c[nt][0] - m0); s0 += c[nt][0];
            c[nt][1] = __expf(c[nt][1] - m0); s0 += c[nt][1];
            c[nt][2] = __expf(c[nt][2] - m1); s1 += c[nt][2];
            c[nt][3] = __expf(c[nt][3] - m1); s1 += c[nt][3];
        }
        s0 += __shfl_xor_sync(0xffffffffu, s0, 1);
        s0 += __shfl_xor_sync(0xffffffffu, s0, 2);
        s1 += __shfl_xor_sync(0xffffffffu, s1, 1);
        s1 += __shfl_xor_sync(0xffffffffu, s1, 2);
        const float inv0 = 1.f / s0, inv1 = 1.f / s1;
#pragma unroll
        for (int nt = 0; nt < 8; nt++) {
            c[nt][0] *= inv0; c[nt][1] *= inv0;
            c[nt][2] *= inv1; c[nt][3] *= inv1;
        }

#pragma unroll
        for (int kt = 0; kt < 4; kt++) {
            uint32_t ph[4];
            ph[0] = pack_h2(c[2 * kt][0],     c[2 * kt][1]);
            ph[1] = pack_h2(c[2 * kt][2],     c[2 * kt][3]);
            ph[2] = pack_h2(c[2 * kt + 1][0], c[2 * kt + 1][1]);
            ph[3] = pack_h2(c[2 * kt + 1][2], c[2 * kt + 1][3]);
#pragma unroll
            for (int nt = 0; nt < 4; nt++) {
                int dn = nt * 8 + gid;
                uint32_t b0 = VTH[dn * 33 + kt * 8 + t4];
                uint32_t b1 = VTH[dn * 33 + kt * 8 + t4 + 4];
                mma16816(o[mt][nt], ph[0], ph[1], ph[2], ph[3], b0, b1);
            }
        }
    }

#pragma unroll
    for (int mt = 0; mt < 4; mt++) {
        int i0 = mt * 16 + gid, i1 = i0 + 8;
#pragma unroll
        for (int nt = 0; nt < 4; nt++) {
            int d = nt * 8 + 2 * t4;
            if (i0 < NTOK) {
                *(uint32_t*)(out + ((size_t)win * NTOK + i0) * CH + head * HD + d) =
                    pack_h2(o[mt][nt][0], o[mt][nt][1]);
            }
            if (i1 < NTOK) {
                *(uint32_t*)(out + ((size_t)win * NTOK + i1) * CH + head * HD + d) =
                    pack_h2(o[mt][nt][2], o[mt][nt][3]);
            }
        }
    }
}

extern "C" void kernel_launch(void* const* d_in, const int* in_sizes, int n_in,
                              void* d_out, int out_size) {
    const float* x      = (const float*)d_in[0];
    const float* qkv_w  = (const float*)d_in[1];
    const float* qkv_b  = (const float*)d_in[2];
    const float* proj_w = (const float*)d_in[3];
    const float* proj_b = (const float*)d_in[4];
    const float* table  = (const float*)d_in[5];
    float* out = (float*)d_out;

    __half *xh, *wq, *wp, *qkv_buf, *attn_buf;
    cudaGetSymbolAddress((void**)&xh, g_xh);
    cudaGetSymbolAddress((void**)&wq, g_wq);
    cudaGetSymbolAddress((void**)&wp, g_wp);
    cudaGetSymbolAddress((void**)&qkv_buf, g_qkv);
    cudaGetSymbolAddress((void**)&attn_buf, g_attnout);

    cudaFuncSetAttribute(tc_gemm<0>, cudaFuncAttributeMaxDynamicSharedMemorySize, SMEM_GEMM);
    cudaFuncSetAttribute(tc_gemm<1>, cudaFuncAttributeMaxDynamicSharedMemorySize, SMEM_GEMM);
    cudaFuncSetAttribute(attn_mma_kernel, cudaFuncAttributeMaxDynamicSharedMemorySize, SMEM_ATTN);

    prep_x<<<(M_TOTAL * (CH / 4)) / 256, 256>>>(x);
    prep_w<<<(QKV_N * CH / 4) / 256, 256>>>(qkv_w, wq);
    prep_w<<<(CH * CH / 4) / 256, 256>>>(proj_w, wp);

    dim3 g1(QKV_N / 128, M_TOTAL / 128);   // (6, 1568)
    tc_gemm<0><<<g1, 256, SMEM_GEMM>>>(xh, wq, qkv_b, qkv_buf);

    attn_mma_kernel<<<BATCH * NWIN, 256, SMEM_ATTN>>>(qkv_buf, table, attn_buf);

    dim3 g3(CH / 128, M_TOTAL / 128);      // (2, 1568)
    tc_gemm<1><<<g3, 256, SMEM_GEMM>>>(attn_buf, wp, proj_b, out);
}